// round 1
// baseline (speedup 1.0000x reference)
#include <cuda_runtime.h>
#include <math.h>

#define NN 50000
#define NE 800000

// ---------------- scratch (no allocations allowed) ----------------
__device__ float g_f[NN * 64];     // projected features, current layer
__device__ float g_x[NN * 64];     // layer input/output (activations)
__device__ float g_acc[NN * 64];   // aggregation accumulator
__device__ float g_ex[NE * 4];     // per-edge exp values (max H = 4)
__device__ float g_el[NN * 4];
__device__ float g_er[NN * 4];
__device__ float g_m[NN * 4];
__device__ float g_s[NN * 4];

// ---------------- kernels ----------------

// f[N,64] = x[N,K] @ W[K,64]. Block: 16 rows, blockDim (64,4), 4 rows/thread.
// smem: xs[16*K] + Ws[K*64]
__global__ void linear_kernel(const float* __restrict__ x,
                              const float* __restrict__ W,
                              float* __restrict__ f, int N, int K) {
    extern __shared__ float sm[];
    float* xs = sm;            // [16][K]
    float* Ws = sm + 16 * K;   // [K][64]
    const int tx = threadIdx.x;            // 0..63 -> output col
    const int tid = threadIdx.y * 64 + tx; // 0..255
    const int rb = blockIdx.x * 16;

    for (int idx = tid; idx < 16 * K; idx += 256) {
        int r = idx / K, k = idx - r * K;
        int row = rb + r;
        xs[idx] = (row < N) ? x[row * K + k] : 0.f;
    }
    for (int idx = tid; idx < K * 64; idx += 256) Ws[idx] = W[idx];
    __syncthreads();

    float acc0 = 0.f, acc1 = 0.f, acc2 = 0.f, acc3 = 0.f;
    const int rloc = threadIdx.y * 4;
    #pragma unroll 4
    for (int k = 0; k < K; k++) {
        float w = Ws[k * 64 + tx];
        acc0 += xs[(rloc + 0) * K + k] * w;
        acc1 += xs[(rloc + 1) * K + k] * w;
        acc2 += xs[(rloc + 2) * K + k] * w;
        acc3 += xs[(rloc + 3) * K + k] * w;
    }
    float accv[4] = {acc0, acc1, acc2, acc3};
    #pragma unroll
    for (int r = 0; r < 4; r++) {
        int row = rb + rloc + r;
        if (row < N) f[row * 64 + tx] = accv[r];
    }
}

// el[n,h] = sum_d f[n,h,d]*al[h,d]; same for er. One warp per node.
__global__ void scores_kernel(const float* __restrict__ f,
                              const float* __restrict__ al,
                              const float* __restrict__ ar,
                              float* __restrict__ el, float* __restrict__ er,
                              int N, int H) {
    int warp = (blockIdx.x * blockDim.x + threadIdx.x) >> 5;
    int lane = threadIdx.x & 31;
    if (warp >= N) return;
    const float* fr = f + warp * 64;
    float v0 = fr[lane];
    float v1 = fr[lane + 32];
    if (H == 4) {
        // elements [0,32): heads 0..1 ; elements [32,64): heads 2..3 (D=16)
        float pl0 = v0 * al[lane],      pr0 = v0 * ar[lane];
        float pl1 = v1 * al[lane + 32], pr1 = v1 * ar[lane + 32];
        #pragma unroll
        for (int o = 8; o; o >>= 1) {
            pl0 += __shfl_down_sync(0xffffffffu, pl0, o, 16);
            pr0 += __shfl_down_sync(0xffffffffu, pr0, o, 16);
            pl1 += __shfl_down_sync(0xffffffffu, pl1, o, 16);
            pr1 += __shfl_down_sync(0xffffffffu, pr1, o, 16);
        }
        if ((lane & 15) == 0) {
            int hb = lane >> 4;  // 0 or 1
            el[warp * 4 + hb] = pl0;
            er[warp * 4 + hb] = pr0;
            el[warp * 4 + 2 + hb] = pl1;
            er[warp * 4 + 2 + hb] = pr1;
        }
    } else {  // H==1, D=64
        float pl = v0 * al[lane] + v1 * al[lane + 32];
        float pr = v0 * ar[lane] + v1 * ar[lane + 32];
        #pragma unroll
        for (int o = 16; o; o >>= 1) {
            pl += __shfl_down_sync(0xffffffffu, pl, o);
            pr += __shfl_down_sync(0xffffffffu, pr, o);
        }
        if (lane == 0) { el[warp] = pl; er[warp] = pr; }
    }
}

__global__ void init_kernel(float* __restrict__ m, float* __restrict__ s,
                            float* __restrict__ acc, int N, int H) {
    int t = blockIdx.x * blockDim.x + threadIdx.x;
    if (t < N * 64) acc[t] = 0.f;
    if (t < N * H) {
        m[t] = __int_as_float(0xff800000);  // -inf
        s[t] = 0.f;
    }
}

__device__ __forceinline__ void atomicMaxF(float* addr, float v) {
    if (v >= 0.f) atomicMax((int*)addr, __float_as_int(v));
    else          atomicMin((unsigned int*)addr, __float_as_uint(v));
}

__global__ void edgemax_kernel(const int* __restrict__ src,
                               const int* __restrict__ dst,
                               const float* __restrict__ el,
                               const float* __restrict__ er,
                               float* __restrict__ m, int E, int H) {
    int e = blockIdx.x * blockDim.x + threadIdx.x;
    if (e >= E) return;
    int s = src[e], d = dst[e];
    #pragma unroll 4
    for (int h = 0; h < H; h++) {
        float v = el[s * H + h] + er[d * H + h];
        v = v > 0.f ? v : 0.2f * v;       // leaky relu
        atomicMaxF(&m[d * H + h], v);
    }
}

__global__ void expsum_kernel(const int* __restrict__ src,
                              const int* __restrict__ dst,
                              const float* __restrict__ el,
                              const float* __restrict__ er,
                              const float* __restrict__ m,
                              float* __restrict__ ex, float* __restrict__ s,
                              int E, int H) {
    int e = blockIdx.x * blockDim.x + threadIdx.x;
    if (e >= E) return;
    int sn = src[e], d = dst[e];
    #pragma unroll 4
    for (int h = 0; h < H; h++) {
        float v = el[sn * H + h] + er[d * H + h];
        v = v > 0.f ? v : 0.2f * v;
        float x = __expf(v - m[d * H + h]) ;
        // __expf max ulp error can exceed requirement? use expf for safety:
        x = expf(v - m[d * H + h]);
        ex[e * H + h] = x;
        atomicAdd(&s[d * H + h], x);
    }
}

// 16 lanes per edge; lane sub handles floats [4*sub, 4*sub+4) of the 64-wide row.
__global__ void aggregate_kernel(const int* __restrict__ src,
                                 const int* __restrict__ dst,
                                 const float* __restrict__ ex,
                                 const float* __restrict__ f,
                                 float* __restrict__ acc, int E, int H) {
    int t = blockIdx.x * blockDim.x + threadIdx.x;
    int e = t >> 4, sub = t & 15;
    if (e >= E) return;
    int s = src[e], d = dst[e];
    int head = (sub * H) >> 4;  // (sub*4)/(64/H)
    float w = ex[e * H + head];
    float4 v = ((const float4*)(f + s * 64))[sub];
    float* o = acc + d * 64 + sub * 4;
    atomicAdd(o + 0, w * v.x);
    atomicAdd(o + 1, w * v.y);
    atomicAdd(o + 2, w * v.z);
    atomicAdd(o + 3, w * v.w);
}

__global__ void finalize_kernel(const float* __restrict__ acc,
                                const float* __restrict__ s,
                                const float* __restrict__ b,
                                float* __restrict__ out,
                                int N, int H, int do_elu) {
    int t = blockIdx.x * blockDim.x + threadIdx.x;
    if (t >= N * 64) return;
    int n = t >> 6, j = t & 63;
    int h = (j * H) >> 6;  // j / (64/H)
    float sv = s[n * H + h];
    float v = (sv > 0.f) ? acc[t] / sv : 0.f;
    v += b[j];
    if (do_elu) v = v > 0.f ? v : expm1f(v);
    out[t] = v;
}

// ---------------- host ----------------

static void run_layer(const float* xin, int K, const float* W,
                      const float* al, const float* ar, const float* b,
                      int H, int do_elu, float* out,
                      float* f, float* acc, float* ex,
                      float* el, float* er, float* m, float* s,
                      const int* src, const int* dst) {
    dim3 lb(64, 4);
    int lin_blocks = (NN + 15) / 16;
    size_t smem = (size_t)(16 * K + K * 64) * sizeof(float);
    linear_kernel<<<lin_blocks, lb, smem>>>(xin, W, f, NN, K);

    int sc_blocks = (NN * 32 + 255) / 256;
    scores_kernel<<<sc_blocks, 256>>>(f, al, ar, el, er, NN, H);

    int in_blocks = (NN * 64 + 255) / 256;
    init_kernel<<<in_blocks, 256>>>(m, s, acc, NN, H);

    int e_blocks = (NE + 255) / 256;
    edgemax_kernel<<<e_blocks, 256>>>(src, dst, el, er, m, NE, H);
    expsum_kernel<<<e_blocks, 256>>>(src, dst, el, er, m, ex, s, NE, H);

    int ag_blocks = (NE * 16 + 255) / 256;
    aggregate_kernel<<<ag_blocks, 256>>>(src, dst, ex, f, acc, NE, H);

    finalize_kernel<<<in_blocks, 256>>>(acc, s, b, out, NN, H, do_elu);
}

extern "C" void kernel_launch(void* const* d_in, const int* in_sizes, int n_in,
                              void* d_out, int out_size) {
    const float* h   = (const float*)d_in[0];
    const int*   src = (const int*)d_in[1];
    const int*   dst = (const int*)d_in[2];
    const float* W0  = (const float*)d_in[3];
    const float* al0 = (const float*)d_in[4];
    const float* ar0 = (const float*)d_in[5];
    const float* b0  = (const float*)d_in[6];
    const float* W1  = (const float*)d_in[7];
    const float* al1 = (const float*)d_in[8];
    const float* ar1 = (const float*)d_in[9];
    const float* b1  = (const float*)d_in[10];
    const float* W2  = (const float*)d_in[11];
    const float* al2 = (const float*)d_in[12];
    const float* ar2 = (const float*)d_in[13];
    const float* b2  = (const float*)d_in[14];
    float* out = (float*)d_out;

    float *f, *x, *acc, *ex, *el, *er, *m, *s;
    cudaGetSymbolAddress((void**)&f,   g_f);
    cudaGetSymbolAddress((void**)&x,   g_x);
    cudaGetSymbolAddress((void**)&acc, g_acc);
    cudaGetSymbolAddress((void**)&ex,  g_ex);
    cudaGetSymbolAddress((void**)&el,  g_el);
    cudaGetSymbolAddress((void**)&er,  g_er);
    cudaGetSymbolAddress((void**)&m,   g_m);
    cudaGetSymbolAddress((void**)&s,   g_s);

    // layer 0: 128 -> 4x16, ELU
    run_layer(h, 128, W0, al0, ar0, b0, 4, 1, x, f, acc, ex, el, er, m, s, src, dst);
    // layer 1: 64 -> 4x16, ELU
    run_layer(x, 64, W1, al1, ar1, b1, 4, 1, x, f, acc, ex, el, er, m, s, src, dst);
    // layer 2: 64 -> 1x64, no ELU
    run_layer(x, 64, W2, al2, ar2, b2, 1, 0, out, f, acc, ex, el, er, m, s, src, dst);
}

// round 2
// speedup vs baseline: 1.9579x; 1.9579x over previous
#include <cuda_runtime.h>
#include <math.h>

#define NN 50000
#define NE 800000

// ---------------- scratch (no allocations allowed) ----------------
__device__ float g_f[NN * 64];       // projected features, current layer
__device__ float g_x[NN * 64];       // layer activations
__device__ float g_ex[NE * 4];       // per-edge scores/exp at SORTED positions
__device__ float g_el[NN * 4];
__device__ float g_er[NN * 4];
__device__ int   g_srcs[NE];         // src ids sorted by dst
__device__ int   g_deg[NN];
__device__ int   g_rowptr[NN + 1];
__device__ int   g_cursor[NN];

// ---------------- CSR build ----------------

__global__ void zero_deg_kernel(int* __restrict__ deg, int n) {
    int t = blockIdx.x * blockDim.x + threadIdx.x;
    if (t < n) deg[t] = 0;
}

__global__ void hist_kernel(const int* __restrict__ dst, int* __restrict__ deg, int E) {
    int e = blockIdx.x * blockDim.x + threadIdx.x;
    if (e < E) atomicAdd(&deg[dst[e]], 1);
}

// single-block exclusive scan over n=NN elements -> rowptr[0..n], cursor copy
__global__ void scan_kernel(const int* __restrict__ deg, int* __restrict__ rowptr,
                            int* __restrict__ cursor, int n) {
    __shared__ int partial[1024];
    const int tid = threadIdx.x;
    const int CH = (n + 1023) / 1024;
    int beg = tid * CH;
    int end = beg + CH; if (end > n) end = n; if (beg > n) beg = n;
    int sum = 0;
    for (int i = beg; i < end; i++) sum += deg[i];
    partial[tid] = sum;
    __syncthreads();
    for (int off = 1; off < 1024; off <<= 1) {
        int v = (tid >= off) ? partial[tid - off] : 0;
        __syncthreads();
        partial[tid] += v;
        __syncthreads();
    }
    int run = (tid > 0) ? partial[tid - 1] : 0;
    for (int i = beg; i < end; i++) {
        rowptr[i] = run;
        cursor[i] = run;
        run += deg[i];
    }
    if (tid == 1023) rowptr[n] = partial[1023];
}

__global__ void scatter_kernel(const int* __restrict__ src, const int* __restrict__ dst,
                               int* __restrict__ cursor, int* __restrict__ srcs, int E) {
    int e = blockIdx.x * blockDim.x + threadIdx.x;
    if (e >= E) return;
    int pos = atomicAdd(&cursor[dst[e]], 1);
    srcs[pos] = src[e];
}

// ---------------- per-layer kernels ----------------

// f[N,64] = x[N,K] @ W[K,64]. Block: 16 rows, blockDim (64,4), 4 rows/thread.
__global__ void linear_kernel(const float* __restrict__ x,
                              const float* __restrict__ W,
                              float* __restrict__ f, int N, int K) {
    extern __shared__ float sm[];
    float* xs = sm;            // [16][K]
    float* Ws = sm + 16 * K;   // [K][64]
    const int tx = threadIdx.x;
    const int tid = threadIdx.y * 64 + tx;
    const int rb = blockIdx.x * 16;

    for (int idx = tid; idx < 16 * K; idx += 256) {
        int r = idx / K, k = idx - r * K;
        int row = rb + r;
        xs[idx] = (row < N) ? x[row * K + k] : 0.f;
    }
    for (int idx = tid; idx < K * 64; idx += 256) Ws[idx] = W[idx];
    __syncthreads();

    float acc0 = 0.f, acc1 = 0.f, acc2 = 0.f, acc3 = 0.f;
    const int rloc = threadIdx.y * 4;
    #pragma unroll 4
    for (int k = 0; k < K; k++) {
        float w = Ws[k * 64 + tx];
        acc0 += xs[(rloc + 0) * K + k] * w;
        acc1 += xs[(rloc + 1) * K + k] * w;
        acc2 += xs[(rloc + 2) * K + k] * w;
        acc3 += xs[(rloc + 3) * K + k] * w;
    }
    float accv[4] = {acc0, acc1, acc2, acc3};
    #pragma unroll
    for (int r = 0; r < 4; r++) {
        int row = rb + rloc + r;
        if (row < N) f[row * 64 + tx] = accv[r];
    }
}

// el[n,h] = sum_d f[n,h,d]*al[h,d]; same for er. One warp per node.
__global__ void scores_kernel(const float* __restrict__ f,
                              const float* __restrict__ al,
                              const float* __restrict__ ar,
                              float* __restrict__ el, float* __restrict__ er,
                              int N, int H) {
    int warp = (blockIdx.x * blockDim.x + threadIdx.x) >> 5;
    int lane = threadIdx.x & 31;
    if (warp >= N) return;
    const float* fr = f + warp * 64;
    float v0 = fr[lane];
    float v1 = fr[lane + 32];
    if (H == 4) {
        float pl0 = v0 * al[lane],      pr0 = v0 * ar[lane];
        float pl1 = v1 * al[lane + 32], pr1 = v1 * ar[lane + 32];
        #pragma unroll
        for (int o = 8; o; o >>= 1) {
            pl0 += __shfl_down_sync(0xffffffffu, pl0, o, 16);
            pr0 += __shfl_down_sync(0xffffffffu, pr0, o, 16);
            pl1 += __shfl_down_sync(0xffffffffu, pl1, o, 16);
            pr1 += __shfl_down_sync(0xffffffffu, pr1, o, 16);
        }
        if ((lane & 15) == 0) {
            int hb = lane >> 4;
            el[warp * 4 + hb] = pl0;
            er[warp * 4 + hb] = pr0;
            el[warp * 4 + 2 + hb] = pl1;
            er[warp * 4 + 2 + hb] = pr1;
        }
    } else {
        float pl = v0 * al[lane] + v1 * al[lane + 32];
        float pr = v0 * ar[lane] + v1 * ar[lane + 32];
        #pragma unroll
        for (int o = 16; o; o >>= 1) {
            pl += __shfl_down_sync(0xffffffffu, pl, o);
            pr += __shfl_down_sync(0xffffffffu, pr, o);
        }
        if (lane == 0) { el[warp] = pl; er[warp] = pr; }
    }
}

// Fused segment softmax + aggregation + bias + ELU. One warp per dst node.
template <int H>
__global__ void gat_node_kernel(const int* __restrict__ rowptr,
                                const int* __restrict__ srcs,
                                const float* __restrict__ f,
                                const float* __restrict__ el,
                                const float* __restrict__ er,
                                float* __restrict__ ex,
                                const float* __restrict__ b,
                                float* __restrict__ out,
                                int N, int do_elu) {
    int warp = (blockIdx.x * blockDim.x + threadIdx.x) >> 5;
    int lane = threadIdx.x & 31;
    if (warp >= N) return;
    const int beg = rowptr[warp], end = rowptr[warp + 1];

    float erv[H];
    #pragma unroll
    for (int h = 0; h < H; h++) erv[h] = er[warp * H + h];

    // Phase A: scores + per-lane max (lanes parallel over edges)
    float mx[H];
    #pragma unroll
    for (int h = 0; h < H; h++) mx[h] = -1e30f;
    for (int i = beg + lane; i < end; i += 32) {
        int s = srcs[i];
        #pragma unroll
        for (int h = 0; h < H; h++) {
            float v = el[s * H + h] + erv[h];
            v = v > 0.f ? v : 0.2f * v;
            ex[i * H + h] = v;
            mx[h] = fmaxf(mx[h], v);
        }
    }
    #pragma unroll
    for (int h = 0; h < H; h++)
        #pragma unroll
        for (int o = 16; o; o >>= 1)
            mx[h] = fmaxf(mx[h], __shfl_xor_sync(0xffffffffu, mx[h], o));

    // Phase B: exp + sum
    float sm[H];
    #pragma unroll
    for (int h = 0; h < H; h++) sm[h] = 0.f;
    for (int i = beg + lane; i < end; i += 32) {
        #pragma unroll
        for (int h = 0; h < H; h++) {
            float x = expf(ex[i * H + h] - mx[h]);
            ex[i * H + h] = x;
            sm[h] += x;
        }
    }
    #pragma unroll
    for (int h = 0; h < H; h++)
        #pragma unroll
        for (int o = 16; o; o >>= 1)
            sm[h] += __shfl_xor_sync(0xffffffffu, sm[h], o);
    float inv[H];
    #pragma unroll
    for (int h = 0; h < H; h++) inv[h] = (sm[h] > 0.f) ? 1.f / sm[h] : 0.f;

    // Phase C: feature aggregation. Lane owns dims [2*lane, 2*lane+1].
    const int hh = (lane * H) >> 5;  // head for this lane's dim pair
    float ax = 0.f, ay = 0.f;
    const float2* frows = (const float2*)f;
    for (int i = beg; i < end; i++) {
        int s = srcs[i];                 // broadcast across warp
        float w = ex[i * H + hh];
        float2 v = frows[s * 32 + lane];
        ax += w * v.x;
        ay += w * v.y;
    }
    ax = ax * inv[hh] + b[2 * lane];
    ay = ay * inv[hh] + b[2 * lane + 1];
    if (do_elu) {
        ax = ax > 0.f ? ax : expm1f(ax);
        ay = ay > 0.f ? ay : expm1f(ay);
    }
    float2 r; r.x = ax; r.y = ay;
    ((float2*)out)[warp * 32 + lane] = r;
}

// ---------------- host ----------------

static void run_layer(const float* xin, int K, const float* W,
                      const float* al, const float* ar, const float* b,
                      int H, int do_elu, float* out,
                      float* f, float* ex, float* el, float* er,
                      const int* rowptr, const int* srcs) {
    dim3 lb(64, 4);
    int lin_blocks = (NN + 15) / 16;
    size_t smem = (size_t)(16 * K + K * 64) * sizeof(float);
    linear_kernel<<<lin_blocks, lb, smem>>>(xin, W, f, NN, K);

    int sc_blocks = (NN * 32 + 255) / 256;
    scores_kernel<<<sc_blocks, 256>>>(f, al, ar, el, er, NN, H);

    int nd_blocks = (NN * 32 + 255) / 256;
    if (H == 4)
        gat_node_kernel<4><<<nd_blocks, 256>>>(rowptr, srcs, f, el, er, ex, b, out, NN, do_elu);
    else
        gat_node_kernel<1><<<nd_blocks, 256>>>(rowptr, srcs, f, el, er, ex, b, out, NN, do_elu);
}

extern "C" void kernel_launch(void* const* d_in, const int* in_sizes, int n_in,
                              void* d_out, int out_size) {
    const float* h   = (const float*)d_in[0];
    const int*   src = (const int*)d_in[1];
    const int*   dst = (const int*)d_in[2];
    const float* W0  = (const float*)d_in[3];
    const float* al0 = (const float*)d_in[4];
    const float* ar0 = (const float*)d_in[5];
    const float* b0  = (const float*)d_in[6];
    const float* W1  = (const float*)d_in[7];
    const float* al1 = (const float*)d_in[8];
    const float* ar1 = (const float*)d_in[9];
    const float* b1  = (const float*)d_in[10];
    const float* W2  = (const float*)d_in[11];
    const float* al2 = (const float*)d_in[12];
    const float* ar2 = (const float*)d_in[13];
    const float* b2  = (const float*)d_in[14];
    float* out = (float*)d_out;

    float *f, *x, *ex, *el, *er;
    int *srcs, *deg, *rowptr, *cursor;
    cudaGetSymbolAddress((void**)&f,      g_f);
    cudaGetSymbolAddress((void**)&x,      g_x);
    cudaGetSymbolAddress((void**)&ex,     g_ex);
    cudaGetSymbolAddress((void**)&el,     g_el);
    cudaGetSymbolAddress((void**)&er,     g_er);
    cudaGetSymbolAddress((void**)&srcs,   g_srcs);
    cudaGetSymbolAddress((void**)&deg,    g_deg);
    cudaGetSymbolAddress((void**)&rowptr, g_rowptr);
    cudaGetSymbolAddress((void**)&cursor, g_cursor);

    // ---- build dst-sorted CSR (once; reused by all 3 layers) ----
    zero_deg_kernel<<<(NN + 255) / 256, 256>>>(deg, NN);
    hist_kernel<<<(NE + 255) / 256, 256>>>(dst, deg, NE);
    scan_kernel<<<1, 1024>>>(deg, rowptr, cursor, NN);
    scatter_kernel<<<(NE + 255) / 256, 256>>>(src, dst, cursor, srcs, NE);

    // layer 0: 128 -> 4x16, ELU
    run_layer(h, 128, W0, al0, ar0, b0, 4, 1, x, f, ex, el, er, rowptr, srcs);
    // layer 1: 64 -> 4x16, ELU
    run_layer(x, 64, W1, al1, ar1, b1, 4, 1, x, f, ex, el, er, rowptr, srcs);
    // layer 2: 64 -> 1x64, no ELU
    run_layer(x, 64, W2, al2, ar2, b2, 1, 0, out, f, ex, el, er, rowptr, srcs);
}

// round 6
// speedup vs baseline: 2.3314x; 1.1908x over previous
#include <cuda_runtime.h>
#include <math.h>

#define NN 50000
#define NE 800000

// ---------------- scratch (no allocations allowed) ----------------
__device__ float g_f[NN * 64];
__device__ float g_x[NN * 64];
__device__ float g_ex[NE * 4];
__device__ float g_el[NN * 4];
__device__ float g_er[NN * 4];
__device__ int   g_srcs[NE];
__device__ int   g_deg[NN];
__device__ int   g_rowptr[NN + 1];
__device__ int   g_cursor[NN];

// ---------------- CSR build ----------------

__global__ void zero_deg_kernel(int* __restrict__ deg, int n) {
    int t = blockIdx.x * blockDim.x + threadIdx.x;
    if (t < n) deg[t] = 0;
}

__global__ void hist_kernel(const int* __restrict__ dst, int* __restrict__ deg, int E) {
    int e = blockIdx.x * blockDim.x + threadIdx.x;
    if (e < E) atomicAdd(&deg[dst[e]], 1);
}

__global__ void scan_kernel(const int* __restrict__ deg, int* __restrict__ rowptr,
                            int* __restrict__ cursor, int n) {
    __shared__ int partial[1024];
    const int tid = threadIdx.x;
    const int CH = (n + 1023) / 1024;
    int beg = tid * CH;
    int end = beg + CH; if (end > n) end = n; if (beg > n) beg = n;
    int sum = 0;
    for (int i = beg; i < end; i++) sum += deg[i];
    partial[tid] = sum;
    __syncthreads();
    for (int off = 1; off < 1024; off <<= 1) {
        int v = (tid >= off) ? partial[tid - off] : 0;
        __syncthreads();
        partial[tid] += v;
        __syncthreads();
    }
    int run = (tid > 0) ? partial[tid - 1] : 0;
    for (int i = beg; i < end; i++) {
        rowptr[i] = run;
        cursor[i] = run;
        run += deg[i];
    }
    if (tid == 1023) rowptr[n] = partial[1023];
}

__global__ void scatter_kernel(const int* __restrict__ src, const int* __restrict__ dst,
                               int* __restrict__ cursor, int* __restrict__ srcs, int E) {
    int e = blockIdx.x * blockDim.x + threadIdx.x;
    if (e >= E) return;
    int pos = atomicAdd(&cursor[dst[e]], 1);
    srcs[pos] = src[e];
}

// ---------------- register-tiled GEMM: f[N,64] = x[N,K] @ W[K,64] ----------------
// BM=128 rows, BN=64 cols, BK=32; 128 threads, 8x8 outputs per thread.
template <int K>
__global__ void linear_tiled_kernel(const float* __restrict__ x,
                                    const float* __restrict__ W,
                                    float* __restrict__ f, int N) {
    __shared__ float xs[32][132];  // [k][row], padded to dodge conflicts
    __shared__ float Ws[32][64];   // [k][col]
    const int tid = threadIdx.x;       // 0..127
    const int tx = tid & 7;            // col group
    const int ty = tid >> 3;           // row group 0..15
    const int rb = blockIdx.x * 128;
    const int c0 = tx * 8;
    const int r0 = ty * 8;

    float acc[8][8];
    #pragma unroll
    for (int i = 0; i < 8; i++)
        #pragma unroll
        for (int j = 0; j < 8; j++) acc[i][j] = 0.f;

    const int kk = tid & 31;
    const int rr = tid >> 5;

    for (int kb = 0; kb < K; kb += 32) {
        #pragma unroll
        for (int r = 0; r < 128; r += 4) {
            int row = rb + r + rr;
            xs[kk][r + rr] = (row < N) ? x[row * K + kb + kk] : 0.f;
        }
        #pragma unroll
        for (int i = 0; i < 16; i++) {
            int idx = tid + i * 128;
            int k = idx >> 6, c = idx & 63;
            Ws[k][c] = W[(kb + k) * 64 + c];
        }
        __syncthreads();

        #pragma unroll
        for (int k = 0; k < 32; k++) {
            float xv[8], wv[8];
            #pragma unroll
            for (int i = 0; i < 8; i++) xv[i] = xs[k][r0 + i];
            #pragma unroll
            for (int j = 0; j < 8; j++) wv[j] = Ws[k][c0 + j];
            #pragma unroll
            for (int i = 0; i < 8; i++)
                #pragma unroll
                for (int j = 0; j < 8; j++)
                    acc[i][j] = fmaf(xv[i], wv[j], acc[i][j]);
        }
        __syncthreads();
    }

    #pragma unroll
    for (int i = 0; i < 8; i++) {
        int row = rb + r0 + i;
        if (row < N) {
            float4 a = make_float4(acc[i][0], acc[i][1], acc[i][2], acc[i][3]);
            float4 b = make_float4(acc[i][4], acc[i][5], acc[i][6], acc[i][7]);
            float4* p = (float4*)(f + row * 64 + c0);
            p[0] = a;
            p[1] = b;
        }
    }
}

// ---------------- scores ----------------
__global__ void scores_kernel(const float* __restrict__ f,
                              const float* __restrict__ al,
                              const float* __restrict__ ar,
                              float* __restrict__ el, float* __restrict__ er,
                              int N, int H) {
    int warp = (blockIdx.x * blockDim.x + threadIdx.x) >> 5;
    int lane = threadIdx.x & 31;
    if (warp >= N) return;
    const float* fr = f + warp * 64;
    float v0 = fr[lane];
    float v1 = fr[lane + 32];
    if (H == 4) {
        float pl0 = v0 * al[lane],      pr0 = v0 * ar[lane];
        float pl1 = v1 * al[lane + 32], pr1 = v1 * ar[lane + 32];
        #pragma unroll
        for (int o = 8; o; o >>= 1) {
            pl0 += __shfl_down_sync(0xffffffffu, pl0, o, 16);
            pr0 += __shfl_down_sync(0xffffffffu, pr0, o, 16);
            pl1 += __shfl_down_sync(0xffffffffu, pl1, o, 16);
            pr1 += __shfl_down_sync(0xffffffffu, pr1, o, 16);
        }
        if ((lane & 15) == 0) {
            int hb = lane >> 4;
            el[warp * 4 + hb] = pl0;
            er[warp * 4 + hb] = pr0;
            el[warp * 4 + 2 + hb] = pl1;
            er[warp * 4 + 2 + hb] = pr1;
        }
    } else {
        float pl = v0 * al[lane] + v1 * al[lane + 32];
        float pr = v0 * ar[lane] + v1 * ar[lane + 32];
        #pragma unroll
        for (int o = 16; o; o >>= 1) {
            pl += __shfl_down_sync(0xffffffffu, pl, o);
            pr += __shfl_down_sync(0xffffffffu, pr, o);
        }
        if (lane == 0) { el[warp] = pl; er[warp] = pr; }
    }
}

// ---------------- fused softmax + aggregation, one warp per dst node ----------------
template <int H>
__global__ void gat_node_kernel(const int* __restrict__ rowptr,
                                const int* __restrict__ srcs,
                                const float* __restrict__ f,
                                const float* __restrict__ el,
                                const float* __restrict__ er,
                                float* __restrict__ ex,
                                const float* __restrict__ b,
                                float* __restrict__ out,
                                int N, int do_elu) {
    int warp = (blockIdx.x * blockDim.x + threadIdx.x) >> 5;
    int lane = threadIdx.x & 31;
    if (warp >= N) return;
    const int beg = rowptr[warp], end = rowptr[warp + 1];

    float erv[H];
    #pragma unroll
    for (int h = 0; h < H; h++) erv[h] = er[warp * H + h];

    float mx[H];
    #pragma unroll
    for (int h = 0; h < H; h++) mx[h] = -1e30f;
    for (int i = beg + lane; i < end; i += 32) {
        int s = srcs[i];
        #pragma unroll
        for (int h = 0; h < H; h++) {
            float v = el[s * H + h] + erv[h];
            v = v > 0.f ? v : 0.2f * v;
            ex[i * H + h] = v;
            mx[h] = fmaxf(mx[h], v);
        }
    }
    #pragma unroll
    for (int h = 0; h < H; h++)
        #pragma unroll
        for (int o = 16; o; o >>= 1)
            mx[h] = fmaxf(mx[h], __shfl_xor_sync(0xffffffffu, mx[h], o));

    float sm[H];
    #pragma unroll
    for (int h = 0; h < H; h++) sm[h] = 0.f;
    for (int i = beg + lane; i < end; i += 32) {
        #pragma unroll
        for (int h = 0; h < H; h++) {
            float xv = expf(ex[i * H + h] - mx[h]);
            ex[i * H + h] = xv;
            sm[h] += xv;
        }
    }
    #pragma unroll
    for (int h = 0; h < H; h++)
        #pragma unroll
        for (int o = 16; o; o >>= 1)
            sm[h] += __shfl_xor_sync(0xffffffffu, sm[h], o);
    float inv[H];
    #pragma unroll
    for (int h = 0; h < H; h++) inv[h] = (sm[h] > 0.f) ? 1.f / sm[h] : 0.f;

    // Phase C: lane owns dims [2*lane, 2*lane+1]; 2-way unrolled over edges.
    const int hh = (lane * H) >> 5;
    float ax = 0.f, ay = 0.f;
    const float2* frows = (const float2*)f;
    int i = beg;
    for (; i + 2 <= end; i += 2) {
        int s0 = srcs[i], s1 = srcs[i + 1];
        float w0 = ex[i * H + hh];
        float w1 = ex[(i + 1) * H + hh];
        float2 v0 = frows[s0 * 32 + lane];
        float2 v1 = frows[s1 * 32 + lane];
        ax += w0 * v0.x + w1 * v1.x;
        ay += w0 * v0.y + w1 * v1.y;
    }
    if (i < end) {
        int s0 = srcs[i];
        float w0 = ex[i * H + hh];
        float2 v0 = frows[s0 * 32 + lane];
        ax += w0 * v0.x;
        ay += w0 * v0.y;
    }
    ax = ax * inv[hh] + b[2 * lane];
    ay = ay * inv[hh] + b[2 * lane + 1];
    if (do_elu) {
        ax = ax > 0.f ? ax : expm1f(ax);
        ay = ay > 0.f ? ay : expm1f(ay);
    }
    float2 r; r.x = ax; r.y = ay;
    ((float2*)out)[warp * 32 + lane] = r;
}

// ---------------- host ----------------

static void run_layer(const float* xin, int K, const float* W,
                      const float* al, const float* ar, const float* b,
                      int H, int do_elu, float* out,
                      float* f, float* ex, float* el, float* er,
                      const int* rowptr, const int* srcs) {
    int lin_blocks = (NN + 127) / 128;
    if (K == 128)
        linear_tiled_kernel<128><<<lin_blocks, 128>>>(xin, W, f, NN);
    else
        linear_tiled_kernel<64><<<lin_blocks, 128>>>(xin, W, f, NN);

    int sc_blocks = (NN * 32 + 255) / 256;
    scores_kernel<<<sc_blocks, 256>>>(f, al, ar, el, er, NN, H);

    int nd_blocks = (NN * 32 + 255) / 256;
    if (H == 4)
        gat_node_kernel<4><<<nd_blocks, 256>>>(rowptr, srcs, f, el, er, ex, b, out, NN, do_elu);
    else
        gat_node_kernel<1><<<nd_blocks, 256>>>(rowptr, srcs, f, el, er, ex, b, out, NN, do_elu);
}

extern "C" void kernel_launch(void* const* d_in, const int* in_sizes, int n_in,
                              void* d_out, int out_size) {
    const float* h   = (const float*)d_in[0];
    const int*   src = (const int*)d_in[1];
    const int*   dst = (const int*)d_in[2];
    const float* W0  = (const float*)d_in[3];
    const float* al0 = (const float*)d_in[4];
    const float* ar0 = (const float*)d_in[5];
    const float* b0  = (const float*)d_in[6];
    const float* W1  = (const float*)d_in[7];
    const float* al1 = (const float*)d_in[8];
    const float* ar1 = (const float*)d_in[9];
    const float* b1  = (const float*)d_in[10];
    const float* W2  = (const float*)d_in[11];
    const float* al2 = (const float*)d_in[12];
    const float* ar2 = (const float*)d_in[13];
    const float* b2  = (const float*)d_in[14];
    float* out = (float*)d_out;

    float *f, *x, *ex, *el, *er;
    int *srcs, *deg, *rowptr, *cursor;
    cudaGetSymbolAddress((void**)&f,      g_f);
    cudaGetSymbolAddress((void**)&x,      g_x);
    cudaGetSymbolAddress((void**)&ex,     g_ex);
    cudaGetSymbolAddress((void**)&el,     g_el);
    cudaGetSymbolAddress((void**)&er,     g_er);
    cudaGetSymbolAddress((void**)&srcs,   g_srcs);
    cudaGetSymbolAddress((void**)&deg,    g_deg);
    cudaGetSymbolAddress((void**)&rowptr, g_rowptr);
    cudaGetSymbolAddress((void**)&cursor, g_cursor);

    zero_deg_kernel<<<(NN + 255) / 256, 256>>>(deg, NN);
    hist_kernel<<<(NE + 255) / 256, 256>>>(dst, deg, NE);
    scan_kernel<<<1, 1024>>>(deg, rowptr, cursor, NN);
    scatter_kernel<<<(NE + 255) / 256, 256>>>(src, dst, cursor, srcs, NE);

    run_layer(h, 128, W0, al0, ar0, b0, 4, 1, x, f, ex, el, er, rowptr, srcs);
    run_layer(x, 64, W1, al1, ar1, b1, 4, 1, x, f, ex, el, er, rowptr, srcs);
    run_layer(x, 64, W2, al2, ar2, b2, 1, 0, out, f, ex, el, er, rowptr, srcs);
}

// round 10
// speedup vs baseline: 2.5447x; 1.0915x over previous
#include <cuda_runtime.h>
#include <math.h>

#define NN 50000
#define NE 800000

// ---------------- scratch (no allocations allowed) ----------------
__device__ float g_f[NN * 64];
__device__ float g_x[NN * 64];
__device__ float g_el[NN * 4];
__device__ float g_er[NN * 4];
__device__ float g_elmax[8];     // [2 bufs][4 heads]
__device__ int   g_srcs[NE];
__device__ int   g_deg[NN];
__device__ int   g_rowptr[NN + 1];
__device__ int   g_cursor[NN];

__device__ __forceinline__ float lrelu(float v) { return v > 0.f ? v : 0.2f * v; }

__device__ __forceinline__ float sel4(float4 q, int h) {
    float a = (h == 0) ? q.x : q.y;
    float b = (h == 2) ? q.z : q.w;
    return (h < 2) ? a : b;
}

__device__ __forceinline__ void atomicMaxF(float* addr, float v) {
    if (v >= 0.f) atomicMax((int*)addr, __float_as_int(v));
    else          atomicMin((unsigned int*)addr, __float_as_uint(v));
}

// ---------------- CSR build ----------------

__global__ void zero_deg_kernel(int* __restrict__ deg, float* __restrict__ elmax, int n) {
    int t = blockIdx.x * blockDim.x + threadIdx.x;
    if (t < n) deg[t] = 0;
    if (blockIdx.x == 0 && threadIdx.x < 8) elmax[threadIdx.x] = -1e30f;
}

__global__ void hist_kernel(const int* __restrict__ dst, int* __restrict__ deg, int E) {
    int e = blockIdx.x * blockDim.x + threadIdx.x;
    if (e < E) atomicAdd(&deg[dst[e]], 1);
}

__global__ void scan_kernel(const int* __restrict__ deg, int* __restrict__ rowptr,
                            int* __restrict__ cursor, int n) {
    __shared__ int partial[1024];
    const int tid = threadIdx.x;
    const int CH = (n + 1023) / 1024;
    int beg = tid * CH;
    int end = beg + CH; if (end > n) end = n; if (beg > n) beg = n;
    int sum = 0;
    for (int i = beg; i < end; i++) sum += deg[i];
    partial[tid] = sum;
    __syncthreads();
    for (int off = 1; off < 1024; off <<= 1) {
        int v = (tid >= off) ? partial[tid - off] : 0;
        __syncthreads();
        partial[tid] += v;
        __syncthreads();
    }
    int run = (tid > 0) ? partial[tid - 1] : 0;
    for (int i = beg; i < end; i++) {
        rowptr[i] = run;
        cursor[i] = run;
        run += deg[i];
    }
    if (tid == 1023) rowptr[n] = partial[1023];
}

__global__ void scatter_kernel(const int* __restrict__ src, const int* __restrict__ dst,
                               int* __restrict__ cursor, int* __restrict__ srcs, int E) {
    int e = blockIdx.x * blockDim.x + threadIdx.x;
    if (e >= E) return;
    int pos = atomicAdd(&cursor[dst[e]], 1);
    srcs[pos] = src[e];
}

// ---------------- GEMM + fused score epilogue ----------------
// f[N,64] = x[N,K] @ W[K,64]; el[n,h] = f[n]·al[h]; er likewise; elmax = max_n el.
// BM=128, BN=64, BK=32; 128 threads, 8x8 per thread.
template <int K, int H>
__global__ void linear_tiled_kernel(const float* __restrict__ x,
                                    const float* __restrict__ W,
                                    const float* __restrict__ al,
                                    const float* __restrict__ ar,
                                    float* __restrict__ f,
                                    float* __restrict__ el,
                                    float* __restrict__ er,
                                    float* __restrict__ elmax,
                                    int N) {
    __shared__ float xs[32][132];
    __shared__ float Ws[32][64];
    __shared__ float smax[4];
    const int tid = threadIdx.x;
    const int tx = tid & 7;
    const int ty = tid >> 3;
    const int rb = blockIdx.x * 128;
    const int c0 = tx * 8;
    const int r0 = ty * 8;

    if (tid < 4) smax[tid] = -1e30f;

    float acc[8][8];
    #pragma unroll
    for (int i = 0; i < 8; i++)
        #pragma unroll
        for (int j = 0; j < 8; j++) acc[i][j] = 0.f;

    const int kk = tid & 31;
    const int rr = tid >> 5;

    for (int kb = 0; kb < K; kb += 32) {
        #pragma unroll
        for (int r = 0; r < 128; r += 4) {
            int row = rb + r + rr;
            xs[kk][r + rr] = (row < N) ? x[row * K + kb + kk] : 0.f;
        }
        #pragma unroll
        for (int i = 0; i < 16; i++) {
            int idx = tid + i * 128;
            int k = idx >> 6, c = idx & 63;
            Ws[k][c] = W[(kb + k) * 64 + c];
        }
        __syncthreads();

        #pragma unroll
        for (int k = 0; k < 32; k++) {
            float xv[8], wv[8];
            #pragma unroll
            for (int i = 0; i < 8; i++) xv[i] = xs[k][r0 + i];
            #pragma unroll
            for (int j = 0; j < 8; j++) wv[j] = Ws[k][c0 + j];
            #pragma unroll
            for (int i = 0; i < 8; i++)
                #pragma unroll
                for (int j = 0; j < 8; j++)
                    acc[i][j] = fmaf(xv[i], wv[j], acc[i][j]);
        }
        __syncthreads();
    }

    // store f
    #pragma unroll
    for (int i = 0; i < 8; i++) {
        int row = rb + r0 + i;
        if (row < N) {
            float4 a = make_float4(acc[i][0], acc[i][1], acc[i][2], acc[i][3]);
            float4 b = make_float4(acc[i][4], acc[i][5], acc[i][6], acc[i][7]);
            float4* p = (float4*)(f + row * 64 + c0);
            p[0] = a;
            p[1] = b;
        }
    }

    // fused scores: al/ar flattened [H*D] = 64 floats aligned with output cols
    float al_c[8], ar_c[8];
    #pragma unroll
    for (int j = 0; j < 8; j++) { al_c[j] = al[c0 + j]; ar_c[j] = ar[c0 + j]; }

    float localmax = -1e30f;
    #pragma unroll
    for (int i = 0; i < 8; i++) {
        float pl = 0.f, pr = 0.f;
        #pragma unroll
        for (int j = 0; j < 8; j++) {
            pl = fmaf(acc[i][j], al_c[j], pl);
            pr = fmaf(acc[i][j], ar_c[j], pr);
        }
        int row = rb + r0 + i;
        if (H == 4) {
            pl += __shfl_xor_sync(0xffffffffu, pl, 1);
            pr += __shfl_xor_sync(0xffffffffu, pr, 1);
            if ((tx & 1) == 0 && row < N) {
                int head = tx >> 1;
                el[row * 4 + head] = pl;
                er[row * 4 + head] = pr;
                localmax = fmaxf(localmax, pl);
            }
        } else {
            #pragma unroll
            for (int o = 1; o < 8; o <<= 1) {
                pl += __shfl_xor_sync(0xffffffffu, pl, o);
                pr += __shfl_xor_sync(0xffffffffu, pr, o);
            }
            if (tx == 0 && row < N) {
                el[row] = pl;
                er[row] = pr;
                localmax = fmaxf(localmax, pl);
            }
        }
    }
    // block-level max -> global
    __syncthreads();
    if (localmax > -1e30f) {
        int head = (H == 4) ? (tx >> 1) : 0;
        atomicMaxF(&smax[head], localmax);
    }
    __syncthreads();
    if (tid < H) atomicMaxF(&elmax[tid], smax[tid]);
}

// ---------------- fused single-pass softmax+aggregation, one warp per node ----------------
template <int H>
__global__ void gat_node_kernel(const int* __restrict__ rowptr,
                                const int* __restrict__ srcs,
                                const float* __restrict__ f,
                                const float* __restrict__ el,
                                const float* __restrict__ er,
                                const float* __restrict__ elmax,
                                const float* __restrict__ b,
                                float* __restrict__ out,
                                int N, int do_elu,
                                float* __restrict__ reset_ptr) {
    if (reset_ptr && blockIdx.x == 0 && threadIdx.x < 4)
        reset_ptr[threadIdx.x] = -1e30f;

    int warp = (blockIdx.x * blockDim.x + threadIdx.x) >> 5;
    int lane = threadIdx.x & 31;
    if (warp >= N) return;
    const int beg = rowptr[warp], end = rowptr[warp + 1];

    const int hh = (H == 4) ? (lane >> 3) : 0;
    float er_h, B;
    if (H == 4) {
        float4 er4 = __ldg((const float4*)er + warp);
        float4 em4 = __ldg((const float4*)elmax);
        er_h = sel4(er4, hh);
        B = lrelu(sel4(em4, hh) + er_h);
    } else {
        er_h = __ldg(er + warp);
        B = lrelu(__ldg(elmax) + er_h);
    }

    float ax = 0.f, ay = 0.f, sw = 0.f;
    const float2* frows = (const float2*)f;
    const float4* el4 = (const float4*)el;

    int i = beg;
    for (; i + 4 <= end; i += 4) {
        int s0 = __ldg(srcs + i + 0);
        int s1 = __ldg(srcs + i + 1);
        int s2 = __ldg(srcs + i + 2);
        int s3 = __ldg(srcs + i + 3);
        float e0, e1, e2, e3;
        if (H == 4) {
            e0 = sel4(__ldg(el4 + s0), hh);
            e1 = sel4(__ldg(el4 + s1), hh);
            e2 = sel4(__ldg(el4 + s2), hh);
            e3 = sel4(__ldg(el4 + s3), hh);
        } else {
            e0 = __ldg(el + s0); e1 = __ldg(el + s1);
            e2 = __ldg(el + s2); e3 = __ldg(el + s3);
        }
        float2 v0 = __ldg(frows + s0 * 32 + lane);
        float2 v1 = __ldg(frows + s1 * 32 + lane);
        float2 v2 = __ldg(frows + s2 * 32 + lane);
        float2 v3 = __ldg(frows + s3 * 32 + lane);
        float w0 = __expf(lrelu(e0 + er_h) - B);
        float w1 = __expf(lrelu(e1 + er_h) - B);
        float w2 = __expf(lrelu(e2 + er_h) - B);
        float w3 = __expf(lrelu(e3 + er_h) - B);
        sw += (w0 + w1) + (w2 + w3);
        ax = fmaf(w0, v0.x, ax); ay = fmaf(w0, v0.y, ay);
        ax = fmaf(w1, v1.x, ax); ay = fmaf(w1, v1.y, ay);
        ax = fmaf(w2, v2.x, ax); ay = fmaf(w2, v2.y, ay);
        ax = fmaf(w3, v3.x, ax); ay = fmaf(w3, v3.y, ay);
    }
    for (; i < end; i++) {
        int s0 = __ldg(srcs + i);
        float e0 = (H == 4) ? sel4(__ldg(el4 + s0), hh) : __ldg(el + s0);
        float2 v0 = __ldg(frows + s0 * 32 + lane);
        float w0 = __expf(lrelu(e0 + er_h) - B);
        sw += w0;
        ax = fmaf(w0, v0.x, ax);
        ay = fmaf(w0, v0.y, ay);
    }

    float inv = (sw > 0.f) ? 1.f / sw : 0.f;
    ax = ax * inv + __ldg(b + 2 * lane);
    ay = ay * inv + __ldg(b + 2 * lane + 1);
    if (do_elu) {
        ax = ax > 0.f ? ax : expm1f(ax);
        ay = ay > 0.f ? ay : expm1f(ay);
    }
    float2 r; r.x = ax; r.y = ay;
    ((float2*)out)[warp * 32 + lane] = r;
}

// ---------------- host ----------------

extern "C" void kernel_launch(void* const* d_in, const int* in_sizes, int n_in,
                              void* d_out, int out_size) {
    const float* h   = (const float*)d_in[0];
    const int*   src = (const int*)d_in[1];
    const int*   dst = (const int*)d_in[2];
    const float* W0  = (const float*)d_in[3];
    const float* al0 = (const float*)d_in[4];
    const float* ar0 = (const float*)d_in[5];
    const float* b0  = (const float*)d_in[6];
    const float* W1  = (const float*)d_in[7];
    const float* al1 = (const float*)d_in[8];
    const float* ar1 = (const float*)d_in[9];
    const float* b1  = (const float*)d_in[10];
    const float* W2  = (const float*)d_in[11];
    const float* al2 = (const float*)d_in[12];
    const float* ar2 = (const float*)d_in[13];
    const float* b2  = (const float*)d_in[14];
    float* out = (float*)d_out;

    float *f, *x, *el, *er, *elmax;
    int *srcs, *deg, *rowptr, *cursor;
    cudaGetSymbolAddress((void**)&f,      g_f);
    cudaGetSymbolAddress((void**)&x,      g_x);
    cudaGetSymbolAddress((void**)&el,     g_el);
    cudaGetSymbolAddress((void**)&er,     g_er);
    cudaGetSymbolAddress((void**)&elmax,  g_elmax);
    cudaGetSymbolAddress((void**)&srcs,   g_srcs);
    cudaGetSymbolAddress((void**)&deg,    g_deg);
    cudaGetSymbolAddress((void**)&rowptr, g_rowptr);
    cudaGetSymbolAddress((void**)&cursor, g_cursor);

    float* emax0 = elmax;       // buf 0: layers 0 and 2
    float* emax1 = elmax + 4;   // buf 1: layer 1

    // ---- CSR build (also inits both elmax buffers) ----
    zero_deg_kernel<<<(NN + 255) / 256, 256>>>(deg, elmax, NN);
    hist_kernel<<<(NE + 255) / 256, 256>>>(dst, deg, NE);
    scan_kernel<<<1, 1024>>>(deg, rowptr, cursor, NN);
    scatter_kernel<<<(NE + 255) / 256, 256>>>(src, dst, cursor, srcs, NE);

    const int lin_blocks = (NN + 127) / 128;
    const int nd_blocks = (NN * 32 + 255) / 256;

    // layer 0: 128 -> 4x16, ELU
    linear_tiled_kernel<128, 4><<<lin_blocks, 128>>>(h, W0, al0, ar0, f, el, er, emax0, NN);
    gat_node_kernel<4><<<nd_blocks, 256>>>(rowptr, srcs, f, el, er, emax0, b0, x, NN, 1, nullptr);

    // layer 1: 64 -> 4x16, ELU (its gat_node resets buf0 for layer 2)
    linear_tiled_kernel<64, 4><<<lin_blocks, 128>>>(x, W1, al1, ar1, f, el, er, emax1, NN);
    gat_node_kernel<4><<<nd_blocks, 256>>>(rowptr, srcs, f, el, er, emax1, b1, x, NN, 1, emax0);

    // layer 2: 64 -> 1x64, no ELU
    linear_tiled_kernel<64, 1><<<lin_blocks, 128>>>(x, W2, al2, ar2, f, el, er, emax0, NN);
    gat_node_kernel<1><<<nd_blocks, 256>>>(rowptr, srcs, f, el, er, emax0, b2, out, NN, 0, nullptr);
}

// round 14
// speedup vs baseline: 2.5847x; 1.0157x over previous
#include <cuda_runtime.h>
#include <math.h>

#define NN 50000
#define NE 800000

// ---------------- scratch (no allocations allowed) ----------------
__device__ float g_f[NN * 64];
__device__ float g_x[NN * 64];
__device__ float g_el[NN * 4];
__device__ float g_er[NN * 4];
__device__ float g_elmax[8];     // [2 bufs][4 heads]
__device__ int   g_srcs[NE];
__device__ int   g_deg[NN];
__device__ int   g_rowptr[NN + 1];
__device__ int   g_cursor[NN];

__device__ __forceinline__ float lrelu(float v) { return v > 0.f ? v : 0.2f * v; }

__device__ __forceinline__ float sel4(float4 q, int h) {
    float a = (h == 0) ? q.x : q.y;
    float b = (h == 2) ? q.z : q.w;
    return (h < 2) ? a : b;
}

__device__ __forceinline__ void atomicMaxF(float* addr, float v) {
    if (v >= 0.f) atomicMax((int*)addr, __float_as_int(v));
    else          atomicMin((unsigned int*)addr, __float_as_uint(v));
}

// ---- packed fp32x2 helpers (sm_10x FFMA2 — ptxas won't emit from C++) ----
__device__ __forceinline__ unsigned long long pack2(float x, float y) {
    unsigned long long r;
    asm("mov.b64 %0, {%1, %2};" : "=l"(r) : "f"(x), "f"(y));
    return r;
}
__device__ __forceinline__ void unpack2(unsigned long long v, float& x, float& y) {
    asm("mov.b64 {%0, %1}, %2;" : "=f"(x), "=f"(y) : "l"(v));
}
__device__ __forceinline__ void ffma2(unsigned long long& d,
                                      unsigned long long a,
                                      unsigned long long b) {
    asm("fma.rn.f32x2 %0, %1, %2, %0;" : "+l"(d) : "l"(a), "l"(b));
}

// ---------------- CSR build ----------------

__global__ void zero_deg_kernel(int* __restrict__ deg, float* __restrict__ elmax, int n) {
    int t = blockIdx.x * blockDim.x + threadIdx.x;
    if (t < n) deg[t] = 0;
    if (blockIdx.x == 0 && threadIdx.x < 8) elmax[threadIdx.x] = -1e30f;
}

// 4 edges per thread (E % 4 == 0 for this problem; guarded anyway)
__global__ void hist_kernel(const int* __restrict__ dst, int* __restrict__ deg, int E) {
    int t = blockIdx.x * blockDim.x + threadIdx.x;
    int e = t * 4;
    if (e + 4 <= E) {
        int4 d = __ldg((const int4*)(dst + e));
        atomicAdd(&deg[d.x], 1);
        atomicAdd(&deg[d.y], 1);
        atomicAdd(&deg[d.z], 1);
        atomicAdd(&deg[d.w], 1);
    } else {
        for (; e < E; e++) atomicAdd(&deg[dst[e]], 1);
    }
}

__global__ void scan_kernel(const int* __restrict__ deg, int* __restrict__ rowptr,
                            int* __restrict__ cursor, int n) {
    __shared__ int partial[1024];
    const int tid = threadIdx.x;
    const int CH = (n + 1023) / 1024;
    int beg = tid * CH;
    int end = beg + CH; if (end > n) end = n; if (beg > n) beg = n;
    int sum = 0;
    for (int i = beg; i < end; i++) sum += deg[i];
    partial[tid] = sum;
    __syncthreads();
    for (int off = 1; off < 1024; off <<= 1) {
        int v = (tid >= off) ? partial[tid - off] : 0;
        __syncthreads();
        partial[tid] += v;
        __syncthreads();
    }
    int run = (tid > 0) ? partial[tid - 1] : 0;
    for (int i = beg; i < end; i++) {
        rowptr[i] = run;
        cursor[i] = run;
        run += deg[i];
    }
    if (tid == 1023) rowptr[n] = partial[1023];
}

__global__ void scatter_kernel(const int* __restrict__ src, const int* __restrict__ dst,
                               int* __restrict__ cursor, int* __restrict__ srcs, int E) {
    int t = blockIdx.x * blockDim.x + threadIdx.x;
    int e = t * 4;
    if (e + 4 <= E) {
        int4 s = __ldg((const int4*)(src + e));
        int4 d = __ldg((const int4*)(dst + e));
        int p0 = atomicAdd(&cursor[d.x], 1);
        int p1 = atomicAdd(&cursor[d.y], 1);
        int p2 = atomicAdd(&cursor[d.z], 1);
        int p3 = atomicAdd(&cursor[d.w], 1);
        srcs[p0] = s.x; srcs[p1] = s.y; srcs[p2] = s.z; srcs[p3] = s.w;
    } else {
        for (; e < E; e++) {
            int pos = atomicAdd(&cursor[dst[e]], 1);
            srcs[pos] = src[e];
        }
    }
}

// ---------------- GEMM (FFMA2) + fused score epilogue ----------------
// f[N,64] = x[N,K] @ W[K,64]; el[n,h] = f[n]·al[h]; er likewise; elmax = max_n el.
// BM=128, BN=64, BK=32; 128 threads; 8 rows x 4 col-pairs (packed f32x2) per thread.
template <int K, int H>
__global__ void linear_tiled_kernel(const float* __restrict__ x,
                                    const float* __restrict__ W,
                                    const float* __restrict__ al,
                                    const float* __restrict__ ar,
                                    float* __restrict__ f,
                                    float* __restrict__ el,
                                    float* __restrict__ er,
                                    float* __restrict__ elmax,
                                    int N) {
    __shared__ float xs[32][132];
    __shared__ float Ws[32][64];
    __shared__ float smax[4];
    const int tid = threadIdx.x;
    const int tx = tid & 7;
    const int ty = tid >> 3;
    const int rb = blockIdx.x * 128;
    const int c0 = tx * 8;
    const int r0 = ty * 8;

    if (tid < 4) smax[tid] = -1e30f;

    unsigned long long accp[8][4];
    #pragma unroll
    for (int i = 0; i < 8; i++)
        #pragma unroll
        for (int j = 0; j < 4; j++) accp[i][j] = 0ull;

    const int kk = tid & 31;
    const int rr = tid >> 5;

    for (int kb = 0; kb < K; kb += 32) {
        #pragma unroll
        for (int r = 0; r < 128; r += 4) {
            int row = rb + r + rr;
            xs[kk][r + rr] = (row < N) ? x[row * K + kb + kk] : 0.f;
        }
        #pragma unroll
        for (int i = 0; i < 16; i++) {
            int idx = tid + i * 128;
            int k = idx >> 6, c = idx & 63;
            Ws[k][c] = W[(kb + k) * 64 + c];
        }
        __syncthreads();

        #pragma unroll
        for (int k = 0; k < 32; k++) {
            unsigned long long xv2[8], wv2[4];
            #pragma unroll
            for (int i = 0; i < 8; i++) {
                float xv = xs[k][r0 + i];
                xv2[i] = pack2(xv, xv);
            }
            #pragma unroll
            for (int j = 0; j < 4; j++)
                wv2[j] = *(const unsigned long long*)&Ws[k][c0 + 2 * j];
            #pragma unroll
            for (int i = 0; i < 8; i++)
                #pragma unroll
                for (int j = 0; j < 4; j++)
                    ffma2(accp[i][j], xv2[i], wv2[j]);
        }
        __syncthreads();
    }

    // unpack accumulators
    float acc[8][8];
    #pragma unroll
    for (int i = 0; i < 8; i++)
        #pragma unroll
        for (int j = 0; j < 4; j++)
            unpack2(accp[i][j], acc[i][2 * j], acc[i][2 * j + 1]);

    // store f
    #pragma unroll
    for (int i = 0; i < 8; i++) {
        int row = rb + r0 + i;
        if (row < N) {
            float4 a = make_float4(acc[i][0], acc[i][1], acc[i][2], acc[i][3]);
            float4 b = make_float4(acc[i][4], acc[i][5], acc[i][6], acc[i][7]);
            float4* p = (float4*)(f + row * 64 + c0);
            p[0] = a;
            p[1] = b;
        }
    }

    // fused scores: al/ar flattened [H*D] = 64 floats aligned with output cols
    float al_c[8], ar_c[8];
    #pragma unroll
    for (int j = 0; j < 8; j++) { al_c[j] = al[c0 + j]; ar_c[j] = ar[c0 + j]; }

    float localmax = -1e30f;
    #pragma unroll
    for (int i = 0; i < 8; i++) {
        float pl = 0.f, pr = 0.f;
        #pragma unroll
        for (int j = 0; j < 8; j++) {
            pl = fmaf(acc[i][j], al_c[j], pl);
            pr = fmaf(acc[i][j], ar_c[j], pr);
        }
        int row = rb + r0 + i;
        if (H == 4) {
            pl += __shfl_xor_sync(0xffffffffu, pl, 1);
            pr += __shfl_xor_sync(0xffffffffu, pr, 1);
            if ((tx & 1) == 0 && row < N) {
                int head = tx >> 1;
                el[row * 4 + head] = pl;
                er[row * 4 + head] = pr;
                localmax = fmaxf(localmax, pl);
            }
        } else {
            #pragma unroll
            for (int o = 1; o < 8; o <<= 1) {
                pl += __shfl_xor_sync(0xffffffffu, pl, o);
                pr += __shfl_xor_sync(0xffffffffu, pr, o);
            }
            if (tx == 0 && row < N) {
                el[row] = pl;
                er[row] = pr;
                localmax = fmaxf(localmax, pl);
            }
        }
    }
    __syncthreads();
    if (localmax > -1e30f) {
        int head = (H == 4) ? (tx >> 1) : 0;
        atomicMaxF(&smax[head], localmax);
    }
    __syncthreads();
    if (tid < H) atomicMaxF(&elmax[tid], smax[tid]);
}

// ---------------- fused single-pass softmax+aggregation, one warp per node ----------------
template <int H>
__global__ void gat_node_kernel(const int* __restrict__ rowptr,
                                const int* __restrict__ srcs,
                                const float* __restrict__ f,
                                const float* __restrict__ el,
                                const float* __restrict__ er,
                                const float* __restrict__ elmax,
                                const float* __restrict__ b,
                                float* __restrict__ out,
                                int N, int do_elu,
                                float* __restrict__ reset_ptr) {
    if (reset_ptr && blockIdx.x == 0 && threadIdx.x < 4)
        reset_ptr[threadIdx.x] = -1e30f;

    int warp = (blockIdx.x * blockDim.x + threadIdx.x) >> 5;
    int lane = threadIdx.x & 31;
    if (warp >= N) return;
    const int beg = rowptr[warp], end = rowptr[warp + 1];

    const int hh = (H == 4) ? (lane >> 3) : 0;
    float er_h, B;
    if (H == 4) {
        float4 er4 = __ldg((const float4*)er + warp);
        float4 em4 = __ldg((const float4*)elmax);
        er_h = sel4(er4, hh);
        B = lrelu(sel4(em4, hh) + er_h);
    } else {
        er_h = __ldg(er + warp);
        B = lrelu(__ldg(elmax) + er_h);
    }

    float ax = 0.f, ay = 0.f, sw = 0.f;
    const float2* frows = (const float2*)f;
    const float4* el4 = (const float4*)el;

    int i = beg;
    // 8-wide batches: all loads independent -> high MLP
    for (; i + 8 <= end; i += 8) {
        int s[8];
        #pragma unroll
        for (int u = 0; u < 8; u++) s[u] = __ldg(srcs + i + u);
        float e[8]; float2 v[8];
        #pragma unroll
        for (int u = 0; u < 8; u++) {
            e[u] = (H == 4) ? sel4(__ldg(el4 + s[u]), hh) : __ldg(el + s[u]);
            v[u] = __ldg(frows + s[u] * 32 + lane);
        }
        #pragma unroll
        for (int u = 0; u < 8; u++) {
            float w = __expf(lrelu(e[u] + er_h) - B);
            sw += w;
            ax = fmaf(w, v[u].x, ax);
            ay = fmaf(w, v[u].y, ay);
        }
    }
    // 4-wide batch
    for (; i + 4 <= end; i += 4) {
        int s[4];
        #pragma unroll
        for (int u = 0; u < 4; u++) s[u] = __ldg(srcs + i + u);
        float e[4]; float2 v[4];
        #pragma unroll
        for (int u = 0; u < 4; u++) {
            e[u] = (H == 4) ? sel4(__ldg(el4 + s[u]), hh) : __ldg(el + s[u]);
            v[u] = __ldg(frows + s[u] * 32 + lane);
        }
        #pragma unroll
        for (int u = 0; u < 4; u++) {
            float w = __expf(lrelu(e[u] + er_h) - B);
            sw += w;
            ax = fmaf(w, v[u].x, ax);
            ay = fmaf(w, v[u].y, ay);
        }
    }
    for (; i < end; i++) {
        int s0 = __ldg(srcs + i);
        float e0 = (H == 4) ? sel4(__ldg(el4 + s0), hh) : __ldg(el + s0);
        float2 v0 = __ldg(frows + s0 * 32 + lane);
        float w0 = __expf(lrelu(e0 + er_h) - B);
        sw += w0;
        ax = fmaf(w0, v0.x, ax);
        ay = fmaf(w0, v0.y, ay);
    }

    float inv = (sw > 0.f) ? 1.f / sw : 0.f;
    ax = ax * inv + __ldg(b + 2 * lane);
    ay = ay * inv + __ldg(b + 2 * lane + 1);
    if (do_elu) {
        ax = ax > 0.f ? ax : expm1f(ax);
        ay = ay > 0.f ? ay : expm1f(ay);
    }
    float2 r; r.x = ax; r.y = ay;
    ((float2*)out)[warp * 32 + lane] = r;
}

// ---------------- host ----------------

extern "C" void kernel_launch(void* const* d_in, const int* in_sizes, int n_in,
                              void* d_out, int out_size) {
    const float* h   = (const float*)d_in[0];
    const int*   src = (const int*)d_in[1];
    const int*   dst = (const int*)d_in[2];
    const float* W0  = (const float*)d_in[3];
    const float* al0 = (const float*)d_in[4];
    const float* ar0 = (const float*)d_in[5];
    const float* b0  = (const float*)d_in[6];
    const float* W1  = (const float*)d_in[7];
    const float* al1 = (const float*)d_in[8];
    const float* ar1 = (const float*)d_in[9];
    const float* b1  = (const float*)d_in[10];
    const float* W2  = (const float*)d_in[11];
    const float* al2 = (const float*)d_in[12];
    const float* ar2 = (const float*)d_in[13];
    const float* b2  = (const float*)d_in[14];
    float* out = (float*)d_out;

    float *f, *x, *el, *er, *elmax;
    int *srcs, *deg, *rowptr, *cursor;
    cudaGetSymbolAddress((void**)&f,      g_f);
    cudaGetSymbolAddress((void**)&x,      g_x);
    cudaGetSymbolAddress((void**)&el,     g_el);
    cudaGetSymbolAddress((void**)&er,     g_er);
    cudaGetSymbolAddress((void**)&elmax,  g_elmax);
    cudaGetSymbolAddress((void**)&srcs,   g_srcs);
    cudaGetSymbolAddress((void**)&deg,    g_deg);
    cudaGetSymbolAddress((void**)&rowptr, g_rowptr);
    cudaGetSymbolAddress((void**)&cursor, g_cursor);

    float* emax0 = elmax;       // buf 0: layers 0 and 2
    float* emax1 = elmax + 4;   // buf 1: layer 1

    // ---- CSR build (also inits both elmax buffers) ----
    zero_deg_kernel<<<(NN + 255) / 256, 256>>>(deg, elmax, NN);
    hist_kernel<<<(NE / 4 + 255) / 256, 256>>>(dst, deg, NE);
    scan_kernel<<<1, 1024>>>(deg, rowptr, cursor, NN);
    scatter_kernel<<<(NE / 4 + 255) / 256, 256>>>(src, dst, cursor, srcs, NE);

    const int lin_blocks = (NN + 127) / 128;
    const int nd_blocks = (NN * 32 + 255) / 256;

    // layer 0: 128 -> 4x16, ELU
    linear_tiled_kernel<128, 4><<<lin_blocks, 128>>>(h, W0, al0, ar0, f, el, er, emax0, NN);
    gat_node_kernel<4><<<nd_blocks, 256>>>(rowptr, srcs, f, el, er, emax0, b0, x, NN, 1, nullptr);

    // layer 1: 64 -> 4x16, ELU (its gat_node resets buf0 for layer 2)
    linear_tiled_kernel<64, 4><<<lin_blocks, 128>>>(x, W1, al1, ar1, f, el, er, emax1, NN);
    gat_node_kernel<4><<<nd_blocks, 256>>>(rowptr, srcs, f, el, er, emax1, b1, x, NN, 1, emax0);

    // layer 2: 64 -> 1x64, no ELU
    linear_tiled_kernel<64, 1><<<lin_blocks, 128>>>(x, W2, al2, ar2, f, el, er, emax0, NN);
    gat_node_kernel<1><<<nd_blocks, 256>>>(rowptr, srcs, f, el, er, emax0, b2, out, NN, 0, nullptr);
}

// round 15
// speedup vs baseline: 2.8438x; 1.1003x over previous
#include <cuda_runtime.h>
#include <math.h>

#define NN 50000
#define NE 800000

// ---------------- scratch (no allocations allowed) ----------------
__device__ float g_f[NN * 64];
__device__ float g_x[NN * 64];
__device__ float g_el[NN * 4];
__device__ float g_er[NN * 4];
__device__ float g_elmax[8];     // [2 bufs][4 heads]
__device__ int   g_srcs[NE];
__device__ int   g_deg[NN];
__device__ int   g_rowptr[NN + 1];
__device__ int   g_cursor[NN];

__device__ __forceinline__ float lrelu(float v) { return v > 0.f ? v : 0.2f * v; }

__device__ __forceinline__ float sel4(float4 q, int h) {
    float a = (h == 0) ? q.x : q.y;
    float b = (h == 2) ? q.z : q.w;
    return (h < 2) ? a : b;
}

__device__ __forceinline__ void atomicMaxF(float* addr, float v) {
    if (v >= 0.f) atomicMax((int*)addr, __float_as_int(v));
    else          atomicMin((unsigned int*)addr, __float_as_uint(v));
}

// ---- packed fp32x2 helpers (sm_10x FFMA2) ----
__device__ __forceinline__ unsigned long long pack2(float x, float y) {
    unsigned long long r;
    asm("mov.b64 %0, {%1, %2};" : "=l"(r) : "f"(x), "f"(y));
    return r;
}
__device__ __forceinline__ void unpack2(unsigned long long v, float& x, float& y) {
    asm("mov.b64 {%0, %1}, %2;" : "=f"(x), "=f"(y) : "l"(v));
}
__device__ __forceinline__ void ffma2(unsigned long long& d,
                                      unsigned long long a,
                                      unsigned long long b) {
    asm("fma.rn.f32x2 %0, %1, %2, %0;" : "+l"(d) : "l"(a), "l"(b));
}

// ---------------- CSR build ----------------

// 4 edges per thread; block 0 also initializes both elmax buffers.
__global__ void hist_kernel(const int* __restrict__ dst, int* __restrict__ deg,
                            float* __restrict__ elmax, int E) {
    if (blockIdx.x == 0 && threadIdx.x < 8) elmax[threadIdx.x] = -1e30f;
    int t = blockIdx.x * blockDim.x + threadIdx.x;
    int e = t * 4;
    if (e + 4 <= E) {
        int4 d = __ldg((const int4*)(dst + e));
        atomicAdd(&deg[d.x], 1);
        atomicAdd(&deg[d.y], 1);
        atomicAdd(&deg[d.z], 1);
        atomicAdd(&deg[d.w], 1);
    } else {
        for (; e < E; e++) atomicAdd(&deg[dst[e]], 1);
    }
}

// single-block scan with shuffle-based block scan (2 barriers).
__global__ void scan_kernel(const int* __restrict__ deg, int* __restrict__ rowptr,
                            int* __restrict__ cursor, int n) {
    __shared__ int wsum[32];
    const int tid = threadIdx.x;
    const int lane = tid & 31;
    const int wid = tid >> 5;
    const int CH = (n + 1023) / 1024;
    int beg = tid * CH;
    int end = beg + CH; if (end > n) end = n; if (beg > n) beg = n;
    int sum = 0;
    for (int i = beg; i < end; i++) sum += deg[i];

    // warp inclusive scan
    int v = sum;
    #pragma unroll
    for (int o = 1; o < 32; o <<= 1) {
        int u = __shfl_up_sync(0xffffffffu, v, o);
        if (lane >= o) v += u;
    }
    if (lane == 31) wsum[wid] = v;
    __syncthreads();
    if (wid == 0) {
        int w = wsum[lane];
        #pragma unroll
        for (int o = 1; o < 32; o <<= 1) {
            int u = __shfl_up_sync(0xffffffffu, w, o);
            if (lane >= o) w += u;
        }
        wsum[lane] = w;
    }
    __syncthreads();

    int run = v - sum + (wid > 0 ? wsum[wid - 1] : 0);  // exclusive prefix
    for (int i = beg; i < end; i++) {
        rowptr[i] = run;
        cursor[i] = run;
        run += deg[i];
    }
    if (tid == 1023) rowptr[n] = run;
}

__global__ void scatter_kernel(const int* __restrict__ src, const int* __restrict__ dst,
                               int* __restrict__ cursor, int* __restrict__ srcs, int E) {
    int t = blockIdx.x * blockDim.x + threadIdx.x;
    int e = t * 4;
    if (e + 4 <= E) {
        int4 s = __ldg((const int4*)(src + e));
        int4 d = __ldg((const int4*)(dst + e));
        int p0 = atomicAdd(&cursor[d.x], 1);
        int p1 = atomicAdd(&cursor[d.y], 1);
        int p2 = atomicAdd(&cursor[d.z], 1);
        int p3 = atomicAdd(&cursor[d.w], 1);
        srcs[p0] = s.x; srcs[p1] = s.y; srcs[p2] = s.z; srcs[p3] = s.w;
    } else {
        for (; e < E; e++) {
            int pos = atomicAdd(&cursor[dst[e]], 1);
            srcs[pos] = src[e];
        }
    }
}

// ---------------- GEMM (FFMA2) + fused score epilogue ----------------
template <int K, int H>
__global__ void linear_tiled_kernel(const float* __restrict__ x,
                                    const float* __restrict__ W,
                                    const float* __restrict__ al,
                                    const float* __restrict__ ar,
                                    float* __restrict__ f,
                                    float* __restrict__ el,
                                    float* __restrict__ er,
                                    float* __restrict__ elmax,
                                    int N) {
    __shared__ float xs[32][132];
    __shared__ float Ws[32][64];
    __shared__ float smax[4];
    const int tid = threadIdx.x;
    const int tx = tid & 7;
    const int ty = tid >> 3;
    const int rb = blockIdx.x * 128;
    const int c0 = tx * 8;
    const int r0 = ty * 8;

    if (tid < 4) smax[tid] = -1e30f;

    unsigned long long accp[8][4];
    #pragma unroll
    for (int i = 0; i < 8; i++)
        #pragma unroll
        for (int j = 0; j < 4; j++) accp[i][j] = 0ull;

    const int kk = tid & 31;
    const int rr = tid >> 5;

    for (int kb = 0; kb < K; kb += 32) {
        #pragma unroll
        for (int r = 0; r < 128; r += 4) {
            int row = rb + r + rr;
            xs[kk][r + rr] = (row < N) ? x[row * K + kb + kk] : 0.f;
        }
        #pragma unroll
        for (int i = 0; i < 16; i++) {
            int idx = tid + i * 128;
            int k = idx >> 6, c = idx & 63;
            Ws[k][c] = W[(kb + k) * 64 + c];
        }
        __syncthreads();

        #pragma unroll
        for (int k = 0; k < 32; k++) {
            unsigned long long xv2[8], wv2[4];
            #pragma unroll
            for (int i = 0; i < 8; i++) {
                float xv = xs[k][r0 + i];
                xv2[i] = pack2(xv, xv);
            }
            #pragma unroll
            for (int j = 0; j < 4; j++)
                wv2[j] = *(const unsigned long long*)&Ws[k][c0 + 2 * j];
            #pragma unroll
            for (int i = 0; i < 8; i++)
                #pragma unroll
                for (int j = 0; j < 4; j++)
                    ffma2(accp[i][j], xv2[i], wv2[j]);
        }
        __syncthreads();
    }

    float acc[8][8];
    #pragma unroll
    for (int i = 0; i < 8; i++)
        #pragma unroll
        for (int j = 0; j < 4; j++)
            unpack2(accp[i][j], acc[i][2 * j], acc[i][2 * j + 1]);

    #pragma unroll
    for (int i = 0; i < 8; i++) {
        int row = rb + r0 + i;
        if (row < N) {
            float4 a = make_float4(acc[i][0], acc[i][1], acc[i][2], acc[i][3]);
            float4 b = make_float4(acc[i][4], acc[i][5], acc[i][6], acc[i][7]);
            float4* p = (float4*)(f + row * 64 + c0);
            p[0] = a;
            p[1] = b;
        }
    }

    float al_c[8], ar_c[8];
    #pragma unroll
    for (int j = 0; j < 8; j++) { al_c[j] = al[c0 + j]; ar_c[j] = ar[c0 + j]; }

    float localmax = -1e30f;
    #pragma unroll
    for (int i = 0; i < 8; i++) {
        float pl = 0.f, pr = 0.f;
        #pragma unroll
        for (int j = 0; j < 8; j++) {
            pl = fmaf(acc[i][j], al_c[j], pl);
            pr = fmaf(acc[i][j], ar_c[j], pr);
        }
        int row = rb + r0 + i;
        if (H == 4) {
            pl += __shfl_xor_sync(0xffffffffu, pl, 1);
            pr += __shfl_xor_sync(0xffffffffu, pr, 1);
            if ((tx & 1) == 0 && row < N) {
                int head = tx >> 1;
                el[row * 4 + head] = pl;
                er[row * 4 + head] = pr;
                localmax = fmaxf(localmax, pl);
            }
        } else {
            #pragma unroll
            for (int o = 1; o < 8; o <<= 1) {
                pl += __shfl_xor_sync(0xffffffffu, pl, o);
                pr += __shfl_xor_sync(0xffffffffu, pr, o);
            }
            if (tx == 0 && row < N) {
                el[row] = pl;
                er[row] = pr;
                localmax = fmaxf(localmax, pl);
            }
        }
    }
    __syncthreads();
    if (localmax > -1e30f) {
        int head = (H == 4) ? (tx >> 1) : 0;
        atomicMaxF(&smax[head], localmax);
    }
    __syncthreads();
    if (tid < H) atomicMaxF(&elmax[tid], smax[tid]);
}

// ---------------- fused single-pass softmax+aggregation ----------------
// 2 nodes per warp: lanes 0-15 -> node 2w, lanes 16-31 -> node 2w+1.
// Each lane owns 4 feature dims (float4).
template <int H>
__global__ void gat_node_kernel(const int* __restrict__ rowptr,
                                const int* __restrict__ srcs,
                                const float* __restrict__ f,
                                const float* __restrict__ el,
                                const float* __restrict__ er,
                                const float* __restrict__ elmax,
                                const float* __restrict__ b,
                                float* __restrict__ out,
                                int N, int do_elu,
                                float* __restrict__ reset_ptr) {
    if (reset_ptr && blockIdx.x == 0 && threadIdx.x < 4)
        reset_ptr[threadIdx.x] = -1e30f;

    int t = blockIdx.x * blockDim.x + threadIdx.x;
    int warp = t >> 5;
    int lane = t & 31;
    int half = lane >> 4;
    int hl = lane & 15;          // lane within half-warp: owns dims [4*hl, 4*hl+4)
    int node = warp * 2 + half;
    if (node >= N) return;
    const int beg = rowptr[node], end = rowptr[node + 1];

    const int hh = (H == 4) ? (hl >> 2) : 0;
    float er_h, B;
    if (H == 4) {
        float4 er4 = __ldg((const float4*)er + node);
        float4 em4 = __ldg((const float4*)elmax);
        er_h = sel4(er4, hh);
        B = lrelu(sel4(em4, hh) + er_h);
    } else {
        er_h = __ldg(er + node);
        B = lrelu(__ldg(elmax) + er_h);
    }

    float ax = 0.f, ay = 0.f, az = 0.f, aw = 0.f, sw = 0.f;
    const float4* f4 = (const float4*)f;
    const float4* el4 = (const float4*)el;

    int i = beg;
    for (; i + 4 <= end; i += 4) {
        int s[4];
        #pragma unroll
        for (int u = 0; u < 4; u++) s[u] = __ldg(srcs + i + u);
        float e[4]; float4 v[4];
        #pragma unroll
        for (int u = 0; u < 4; u++) {
            e[u] = (H == 4) ? sel4(__ldg(el4 + s[u]), hh) : __ldg(el + s[u]);
            v[u] = __ldg(f4 + s[u] * 16 + hl);
        }
        #pragma unroll
        for (int u = 0; u < 4; u++) {
            float w = __expf(lrelu(e[u] + er_h) - B);
            sw += w;
            ax = fmaf(w, v[u].x, ax);
            ay = fmaf(w, v[u].y, ay);
            az = fmaf(w, v[u].z, az);
            aw = fmaf(w, v[u].w, aw);
        }
    }
    for (; i < end; i++) {
        int s0 = __ldg(srcs + i);
        float e0 = (H == 4) ? sel4(__ldg(el4 + s0), hh) : __ldg(el + s0);
        float4 v0 = __ldg(f4 + s0 * 16 + hl);
        float w0 = __expf(lrelu(e0 + er_h) - B);
        sw += w0;
        ax = fmaf(w0, v0.x, ax);
        ay = fmaf(w0, v0.y, ay);
        az = fmaf(w0, v0.z, az);
        aw = fmaf(w0, v0.w, aw);
    }

    float inv = (sw > 0.f) ? 1.f / sw : 0.f;
    float4 bb = __ldg((const float4*)b + hl);
    ax = ax * inv + bb.x;
    ay = ay * inv + bb.y;
    az = az * inv + bb.z;
    aw = aw * inv + bb.w;
    if (do_elu) {
        ax = ax > 0.f ? ax : expm1f(ax);
        ay = ay > 0.f ? ay : expm1f(ay);
        az = az > 0.f ? az : expm1f(az);
        aw = aw > 0.f ? aw : expm1f(aw);
    }
    float4 r; r.x = ax; r.y = ay; r.z = az; r.w = aw;
    ((float4*)out)[node * 16 + hl] = r;
}

// ---------------- host ----------------

extern "C" void kernel_launch(void* const* d_in, const int* in_sizes, int n_in,
                              void* d_out, int out_size) {
    const float* h   = (const float*)d_in[0];
    const int*   src = (const int*)d_in[1];
    const int*   dst = (const int*)d_in[2];
    const float* W0  = (const float*)d_in[3];
    const float* al0 = (const float*)d_in[4];
    const float* ar0 = (const float*)d_in[5];
    const float* b0  = (const float*)d_in[6];
    const float* W1  = (const float*)d_in[7];
    const float* al1 = (const float*)d_in[8];
    const float* ar1 = (const float*)d_in[9];
    const float* b1  = (const float*)d_in[10];
    const float* W2  = (const float*)d_in[11];
    const float* al2 = (const float*)d_in[12];
    const float* ar2 = (const float*)d_in[13];
    const float* b2  = (const float*)d_in[14];
    float* out = (float*)d_out;

    float *f, *x, *el, *er, *elmax;
    int *srcs, *deg, *rowptr, *cursor;
    cudaGetSymbolAddress((void**)&f,      g_f);
    cudaGetSymbolAddress((void**)&x,      g_x);
    cudaGetSymbolAddress((void**)&el,     g_el);
    cudaGetSymbolAddress((void**)&er,     g_er);
    cudaGetSymbolAddress((void**)&elmax,  g_elmax);
    cudaGetSymbolAddress((void**)&srcs,   g_srcs);
    cudaGetSymbolAddress((void**)&deg,    g_deg);
    cudaGetSymbolAddress((void**)&rowptr, g_rowptr);
    cudaGetSymbolAddress((void**)&cursor, g_cursor);

    float* emax0 = elmax;       // buf 0: layers 0 and 2
    float* emax1 = elmax + 4;   // buf 1: layer 1

    // ---- CSR build ----
    cudaMemsetAsync(deg, 0, NN * sizeof(int));
    hist_kernel<<<(NE / 4 + 255) / 256, 256>>>(dst, deg, elmax, NE);
    scan_kernel<<<1, 1024>>>(deg, rowptr, cursor, NN);
    scatter_kernel<<<(NE / 4 + 255) / 256, 256>>>(src, dst, cursor, srcs, NE);

    const int lin_blocks = (NN + 127) / 128;
    const int nd_blocks = (NN * 16 + 255) / 256;   // 2 nodes per warp

    // layer 0: 128 -> 4x16, ELU
    linear_tiled_kernel<128, 4><<<lin_blocks, 128>>>(h, W0, al0, ar0, f, el, er, emax0, NN);
    gat_node_kernel<4><<<nd_blocks, 256>>>(rowptr, srcs, f, el, er, emax0, b0, x, NN, 1, nullptr);

    // layer 1: 64 -> 4x16, ELU (its gat_node resets buf0 for layer 2)
    linear_tiled_kernel<64, 4><<<lin_blocks, 128>>>(x, W1, al1, ar1, f, el, er, emax1, NN);
    gat_node_kernel<4><<<nd_blocks, 256>>>(rowptr, srcs, f, el, er, emax1, b1, x, NN, 1, emax0);

    // layer 2: 64 -> 1x64, no ELU
    linear_tiled_kernel<64, 1><<<lin_blocks, 128>>>(x, W2, al2, ar2, f, el, er, emax0, NN);
    gat_node_kernel<1><<<nd_blocks, 256>>>(rowptr, srcs, f, el, er, emax0, b2, out, NN, 0, nullptr);
}